// round 2
// baseline (speedup 1.0000x reference)
#include <cuda_runtime.h>
#include <math.h>

typedef unsigned long long ull;

#define NTHREADS 128

static constexpr int BR    = 64;    // query rows per CTA
static constexpr int BC    = 32;    // key cols per tile
static constexpr int DH    = 64;    // head dim
static constexpr int NSEQ  = 2048;
static constexpr int BH    = 32;    // batch*heads
static constexpr int QTILES = NSEQ / BR;   // 32
static constexpr float SCALE = 0.125f;     // 1/sqrt(64)

// padded smem strides (floats); all multiples of 4 for 16B vector access
static constexpr int QT_STRIDE = BR + 4;   // Qt [DH][QT_STRIDE]  (d-major, r cols)
static constexpr int KT_STRIDE = BC + 4;   // Kt [DH][KT_STRIDE]  (d-major, c cols)
static constexpr int VS_STRIDE = DH + 4;   // Vs [BC][VS_STRIDE]  (c-major, d cols)
static constexpr int PT_STRIDE = BR + 4;   // Pt [BC][PT_STRIDE]  (c-major, r cols)

__device__ __forceinline__ float neg_inf() { return __int_as_float(0xff800000); }

__device__ __forceinline__ ull pack2(float lo, float hi) {
    ull r;
    asm("mov.b64 %0, {%1, %2};" : "=l"(r) : "f"(lo), "f"(hi));
    return r;
}
__device__ __forceinline__ void unpack2(ull v, float& lo, float& hi) {
    asm("mov.b64 {%0, %1}, %2;" : "=f"(lo), "=f"(hi) : "l"(v));
}
__device__ __forceinline__ ull fma2(ull a, ull b, ull c) {
    ull d;
    asm("fma.rn.f32x2 %0, %1, %2, %3;" : "=l"(d) : "l"(a), "l"(b), "l"(c));
    return d;
}
__device__ __forceinline__ ull mul2(ull a, ull b) {
    ull d;
    asm("mul.rn.f32x2 %0, %1, %2;" : "=l"(d) : "l"(a), "l"(b));
    return d;
}

__global__ __launch_bounds__(NTHREADS) void mha_fwd_kernel(
    const float* __restrict__ Qp, const float* __restrict__ Kp,
    const float* __restrict__ Vp, float* __restrict__ Op)
{
    __shared__ float Qt[DH * QT_STRIDE];  // Q^T tile (scaled)
    __shared__ float Kt[DH * KT_STRIDE];  // K^T tile
    __shared__ float Vs[BC * VS_STRIDE];  // V tile
    __shared__ float Pt[BC * PT_STRIDE];  // P^T tile

    const int tid = threadIdx.x;
    const int tx  = tid & 7;    // 0..7
    const int ty  = tid >> 3;   // 0..15
    const int r0  = ty * 4;     // 4 S/O rows per thread
    const int c0  = tx * 4;     // 4 S cols per thread (GEMM1)
    const int d0  = tx * 8;     // 8 O cols per thread (GEMM2)

    // heavy (large qt) CTAs first for load balance
    const int qt = (int)gridDim.x - 1 - (int)blockIdx.x;
    const int bh = (int)blockIdx.y;
    const size_t base = (size_t)bh * NSEQ * DH;
    const float* Qg = Qp + base + (size_t)qt * BR * DH;
    const float* Kg = Kp + base;
    const float* Vg = Vp + base;

    // ---- load Q tile, transposed into smem, scale folded in ----
    for (int t = tid; t < BR * (DH / 4); t += NTHREADS) {
        int r  = t >> 4;
        int d4 = (t & 15) * 4;
        float4 v4 = *(const float4*)(Qg + r * DH + d4);
        Qt[(d4 + 0) * QT_STRIDE + r] = v4.x * SCALE;
        Qt[(d4 + 1) * QT_STRIDE + r] = v4.y * SCALE;
        Qt[(d4 + 2) * QT_STRIDE + r] = v4.z * SCALE;
        Qt[(d4 + 3) * QT_STRIDE + r] = v4.w * SCALE;
    }

    // online-softmax state
    ull o2[4][4];                       // O accum: 4 rows x 4 packed d-pairs
    float m_i[4], l_i[4];
    #pragma unroll
    for (int i = 0; i < 4; ++i) {
        m_i[i] = neg_inf();
        l_i[i] = 0.0f;
        #pragma unroll
        for (int j = 0; j < 4; ++j) o2[i][j] = 0ull;
    }

    const int ktmax = 2 * qt + 1;       // last K tile touching the diagonal

    for (int kt = 0; kt <= ktmax; ++kt) {
        __syncthreads();                // protect Kt/Vs/Pt from prev iteration

        // ---- load K (transposed) and V tiles ----
        const float* Kgt = Kg + (size_t)kt * BC * DH;
        const float* Vgt = Vg + (size_t)kt * BC * DH;
        for (int t = tid; t < BC * (DH / 4); t += NTHREADS) {
            int c  = t >> 4;
            int d4 = (t & 15) * 4;
            float4 kv = *(const float4*)(Kgt + c * DH + d4);
            Kt[(d4 + 0) * KT_STRIDE + c] = kv.x;
            Kt[(d4 + 1) * KT_STRIDE + c] = kv.y;
            Kt[(d4 + 2) * KT_STRIDE + c] = kv.z;
            Kt[(d4 + 3) * KT_STRIDE + c] = kv.w;
            float4 vv = *(const float4*)(Vgt + c * DH + d4);
            *(float4*)(Vs + c * VS_STRIDE + d4) = vv;
        }
        __syncthreads();

        // ---- GEMM1: S = (Q*scale) K^T  (packed f32x2) ----
        ull s2[4][2];
        #pragma unroll
        for (int i = 0; i < 4; ++i) { s2[i][0] = 0ull; s2[i][1] = 0ull; }

        #pragma unroll 4
        for (int d = 0; d < DH; ++d) {
            float4 qv = *(const float4*)(Qt + d * QT_STRIDE + r0);
            ulonglong2 ka = *(const ulonglong2*)(Kt + d * KT_STRIDE + c0);
            ull q2[4];
            q2[0] = pack2(qv.x, qv.x);
            q2[1] = pack2(qv.y, qv.y);
            q2[2] = pack2(qv.z, qv.z);
            q2[3] = pack2(qv.w, qv.w);
            #pragma unroll
            for (int i = 0; i < 4; ++i) {
                s2[i][0] = fma2(q2[i], ka.x, s2[i][0]);
                s2[i][1] = fma2(q2[i], ka.y, s2[i][1]);
            }
        }

        float s[4][4];
        #pragma unroll
        for (int i = 0; i < 4; ++i) {
            unpack2(s2[i][0], s[i][0], s[i][1]);
            unpack2(s2[i][1], s[i][2], s[i][3]);
        }

        // ---- causal mask (only tiles overlapping the diagonal) ----
        if (kt * BC + BC - 1 > qt * BR) {
            #pragma unroll
            for (int i = 0; i < 4; ++i) {
                int qrow = qt * BR + r0 + i;
                #pragma unroll
                for (int j = 0; j < 4; ++j) {
                    int kcol = kt * BC + c0 + j;
                    if (kcol > qrow) s[i][j] = neg_inf();
                }
            }
        }

        // ---- online softmax (row group = 8 lanes sharing ty) ----
        #pragma unroll
        for (int i = 0; i < 4; ++i) {
            float tm = s[i][0];
            tm = fmaxf(tm, s[i][1]);
            tm = fmaxf(tm, s[i][2]);
            tm = fmaxf(tm, s[i][3]);
            tm = fmaxf(tm, __shfl_xor_sync(0xffffffffu, tm, 1));
            tm = fmaxf(tm, __shfl_xor_sync(0xffffffffu, tm, 2));
            tm = fmaxf(tm, __shfl_xor_sync(0xffffffffu, tm, 4));
            float mn = fmaxf(m_i[i], tm);
            float alpha = __expf(m_i[i] - mn);   // -inf -> 0 on first tile
            m_i[i] = mn;
            float rs = 0.0f;
            #pragma unroll
            for (int j = 0; j < 4; ++j) {
                float p = __expf(s[i][j] - mn);  // masked (-inf) -> 0
                s[i][j] = p;
                rs += p;
            }
            rs += __shfl_xor_sync(0xffffffffu, rs, 1);
            rs += __shfl_xor_sync(0xffffffffu, rs, 2);
            rs += __shfl_xor_sync(0xffffffffu, rs, 4);
            l_i[i] = l_i[i] * alpha + rs;
            ull a2 = pack2(alpha, alpha);
            #pragma unroll
            for (int j = 0; j < 4; ++j) o2[i][j] = mul2(o2[i][j], a2);
        }

        // ---- write P^T to smem ----
        #pragma unroll
        for (int j = 0; j < 4; ++j) {
            float4 pr = make_float4(s[0][j], s[1][j], s[2][j], s[3][j]);
            *(float4*)(Pt + (c0 + j) * PT_STRIDE + r0) = pr;
        }
        __syncthreads();

        // ---- GEMM2: O += P V  (packed f32x2) ----
        #pragma unroll 4
        for (int c = 0; c < BC; ++c) {
            float4 pv = *(const float4*)(Pt + c * PT_STRIDE + r0);
            ulonglong2 va = *(const ulonglong2*)(Vs + c * VS_STRIDE + d0);
            ulonglong2 vb = *(const ulonglong2*)(Vs + c * VS_STRIDE + d0 + 4);
            ull v2[4];
            v2[0] = va.x; v2[1] = va.y; v2[2] = vb.x; v2[3] = vb.y;
            ull p2[4];
            p2[0] = pack2(pv.x, pv.x);
            p2[1] = pack2(pv.y, pv.y);
            p2[2] = pack2(pv.z, pv.z);
            p2[3] = pack2(pv.w, pv.w);
            #pragma unroll
            for (int i = 0; i < 4; ++i) {
                #pragma unroll
                for (int j = 0; j < 4; ++j)
                    o2[i][j] = fma2(p2[i], v2[j], o2[i][j]);
            }
        }
    }

    // ---- epilogue: normalize and store ----
    float* Og = Op + base + (size_t)qt * BR * DH;
    #pragma unroll
    for (int i = 0; i < 4; ++i) {
        float o[8];
        unpack2(o2[i][0], o[0], o[1]);
        unpack2(o2[i][1], o[2], o[3]);
        unpack2(o2[i][2], o[4], o[5]);
        unpack2(o2[i][3], o[6], o[7]);
        float inv = 1.0f / l_i[i];
        #pragma unroll
        for (int j = 0; j < 8; ++j) o[j] *= inv;
        float4 lo = make_float4(o[0], o[1], o[2], o[3]);
        float4 hi = make_float4(o[4], o[5], o[6], o[7]);
        *(float4*)(Og + (r0 + i) * DH + d0)     = lo;
        *(float4*)(Og + (r0 + i) * DH + d0 + 4) = hi;
    }
}

extern "C" void kernel_launch(void* const* d_in, const int* in_sizes, int n_in,
                              void* d_out, int out_size) {
    // metadata order: keys, queries, values (all float32 [2,2048,16,64])
    const float* keys    = (const float*)d_in[0];
    const float* queries = (const float*)d_in[1];
    const float* values  = (const float*)d_in[2];
    float* out = (float*)d_out;

    dim3 grid(QTILES, BH);
    mha_fwd_kernel<<<grid, NTHREADS>>>(queries, keys, values, out);
}

// round 5
// speedup vs baseline: 3.8676x; 3.8676x over previous
#include <cuda_runtime.h>
#include <cuda_bf16.h>
#include <stdint.h>

static constexpr int NSEQ = 2048;
static constexpr int BH   = 32;
static constexpr int DH   = 64;
static constexpr int BR   = 64;            // q rows per CTA
static constexpr int BC   = 64;            // k cols per tile
static constexpr int QTILES = NSEQ / BR;   // 32
static constexpr int NELEM  = BH * NSEQ * DH;  // 4194304
static constexpr float SCALE = 0.125f;

// bf16 hi/lo scratch (prepass output). ~48MB total, static __device__ (legal).
__device__ __align__(16) __nv_bfloat16 g_Qhi[NELEM];
__device__ __align__(16) __nv_bfloat16 g_Qlo[NELEM];
__device__ __align__(16) __nv_bfloat16 g_Khi[NELEM];
__device__ __align__(16) __nv_bfloat16 g_Klo[NELEM];
__device__ __align__(16) __nv_bfloat16 g_Vhi[NELEM];
__device__ __align__(16) __nv_bfloat16 g_Vlo[NELEM];

__device__ __forceinline__ float neg_inf() { return __int_as_float(0xff800000); }

// pack (f0 -> low half, f1 -> high half) as bf16x2
__device__ __forceinline__ uint32_t pack_bf16x2(float f0, float f1) {
    uint32_t r;
    asm("cvt.rn.bf16x2.f32 %0, %1, %2;" : "=r"(r) : "f"(f1), "f"(f0));
    return r;
}
__device__ __forceinline__ float bf_lo(uint32_t h) {
    return __bfloat162float(__ushort_as_bfloat16((unsigned short)(h & 0xffffu)));
}
__device__ __forceinline__ float bf_hi(uint32_t h) {
    return __bfloat162float(__ushort_as_bfloat16((unsigned short)(h >> 16)));
}

__device__ __forceinline__ uint32_t smem_u32(const void* p) {
    uint32_t a;
    asm("{ .reg .u64 t; cvta.to.shared.u64 t, %1; cvt.u32.u64 %0, t; }" : "=r"(a) : "l"(p));
    return a;
}

__device__ __forceinline__ void ldsm4(uint32_t addr, uint32_t* r) {
    asm volatile("ldmatrix.sync.aligned.m8n8.x4.shared.b16 {%0,%1,%2,%3}, [%4];"
                 : "=r"(r[0]), "=r"(r[1]), "=r"(r[2]), "=r"(r[3]) : "r"(addr));
}
__device__ __forceinline__ void ldsm4t(uint32_t addr, uint32_t* r) {
    asm volatile("ldmatrix.sync.aligned.m8n8.x4.trans.shared.b16 {%0,%1,%2,%3}, [%4];"
                 : "=r"(r[0]), "=r"(r[1]), "=r"(r[2]), "=r"(r[3]) : "r"(addr));
}
__device__ __forceinline__ void mma_bf16(float* c, const uint32_t* a, uint32_t b0, uint32_t b1) {
    asm volatile("mma.sync.aligned.m16n8k16.row.col.f32.bf16.bf16.f32 "
                 "{%0,%1,%2,%3}, {%4,%5,%6,%7}, {%8,%9}, {%0,%1,%2,%3};"
                 : "+f"(c[0]), "+f"(c[1]), "+f"(c[2]), "+f"(c[3])
                 : "r"(a[0]), "r"(a[1]), "r"(a[2]), "r"(a[3]), "r"(b0), "r"(b1));
}

// ---------------- prepass: fp32 -> bf16 hi/lo split ----------------
__global__ __launch_bounds__(256) void prepass_kernel(
    const float* __restrict__ Q, const float* __restrict__ K, const float* __restrict__ V)
{
    const int t = blockIdx.y;
    const size_t idx = (size_t)blockIdx.x * 256 + threadIdx.x;     // float4 index
    const float4* src = (const float4*)(t == 0 ? Q : (t == 1 ? K : V));
    uint2* hi = (uint2*)(t == 0 ? g_Qhi : (t == 1 ? g_Khi : g_Vhi));
    uint2* lo = (uint2*)(t == 0 ? g_Qlo : (t == 1 ? g_Klo : g_Vlo));

    float4 v = src[idx];
    if (t == 0) { v.x *= SCALE; v.y *= SCALE; v.z *= SCALE; v.w *= SCALE; }
    uint32_t h0 = pack_bf16x2(v.x, v.y);
    uint32_t h1 = pack_bf16x2(v.z, v.w);
    uint32_t l0 = pack_bf16x2(v.x - bf_lo(h0), v.y - bf_hi(h0));
    uint32_t l1 = pack_bf16x2(v.z - bf_lo(h1), v.w - bf_hi(h1));
    hi[idx] = make_uint2(h0, h1);
    lo[idx] = make_uint2(l0, l1);
}

// ---------------- main flash-attention kernel ----------------
// smem tiles: 64 rows x 64 bf16 (128B/row), chunk-swizzled: chunk' = chunk ^ (row&7)
static constexpr int T_QHI = 0;
static constexpr int T_QLO = 8192;
static constexpr int T_KHI = 16384;
static constexpr int T_KLO = 24576;
static constexpr int T_VHI = 32768;
static constexpr int T_VLO = 40960;

__global__ __launch_bounds__(128) void mha_mma_kernel(float* __restrict__ Op)
{
    __shared__ __align__(16) uint8_t sm[49152];
    const uint32_t sb = smem_u32(sm);

    const int tid  = threadIdx.x;
    const int lane = tid & 31;
    const int warp = tid >> 5;
    const int x7   = lane & 7;

    const int qt = (int)gridDim.x - 1 - (int)blockIdx.x;   // heavy CTAs first
    const int bh = (int)blockIdx.y;
    const size_t base = (size_t)bh * NSEQ * DH;
    const size_t qoff = base + (size_t)qt * BR * DH;

    // ---- stage Q tile into smem (swizzled copy) ----
    {
        const uint4* qh = (const uint4*)(g_Qhi + qoff);
        const uint4* ql = (const uint4*)(g_Qlo + qoff);
        #pragma unroll
        for (int i = tid; i < 512; i += 128) {
            int row = i >> 3, ch = i & 7;
            uint32_t so = (uint32_t)(row * 128 + ((ch ^ (row & 7)) << 4));
            *(uint4*)(sm + T_QHI + so) = qh[i];
            *(uint4*)(sm + T_QLO + so) = ql[i];
        }
    }
    __syncthreads();

    // ---- Q fragments -> registers (resident all kernel) ----
    uint32_t qh[4][4], ql[4][4];
    {
        int rQ = ((lane >> 3) & 1) * 8 + x7;
        int cQ = lane >> 4;
        int r0 = warp * 16;
        #pragma unroll
        for (int ks = 0; ks < 4; ++ks) {
            int row = r0 + rQ;
            int ch  = 2 * ks + cQ;
            uint32_t so = (uint32_t)(row * 128 + ((ch ^ (row & 7)) << 4));
            ldsm4(sb + T_QHI + so, qh[ks]);
            ldsm4(sb + T_QLO + so, ql[ks]);
        }
    }

    // per-lane ldsm address pieces
    const int rK = ((lane >> 4) << 3) + x7;          // K b-frag row within 16-row pair
    const int cK = (lane >> 3) & 1;
    const int rV = ((lane >> 3) & 1) * 8 + x7;       // V trans row within 16
    const int cV = lane >> 4;
    uint32_t swzK[4], swzV[4];
    #pragma unroll
    for (int k = 0; k < 4; ++k) {
        swzK[k] = (uint32_t)(((2 * k + cK) ^ x7) << 4);
        swzV[k] = (uint32_t)(((2 * k + cV) ^ x7) << 4);
    }
    const uint32_t kh_base = sb + T_KHI + rK * 128;
    const uint32_t kl_base = sb + T_KLO + rK * 128;
    const uint32_t vh_base = sb + T_VHI + rV * 128;
    const uint32_t vl_base = sb + T_VLO + rV * 128;

    // state
    float oc[8][4];
    #pragma unroll
    for (int i = 0; i < 8; ++i) { oc[i][0] = oc[i][1] = oc[i][2] = oc[i][3] = 0.f; }
    float m0 = neg_inf(), m1 = neg_inf(), lp0 = 0.f, lp1 = 0.f;

    const int ntiles = qt + 1;
    const int row0l  = warp * 16 + (lane >> 2);   // local row (for diagonal mask)
    const int jb     = (lane & 3) * 2;

    for (int kt = 0; kt < ntiles; ++kt) {
        __syncthreads();
        // ---- stage K/V tiles (bf16 hi/lo, swizzled copy) ----
        {
            const size_t toff = base + (size_t)kt * BC * DH;
            const uint4* kh4 = (const uint4*)(g_Khi + toff);
            const uint4* kl4 = (const uint4*)(g_Klo + toff);
            const uint4* vh4 = (const uint4*)(g_Vhi + toff);
            const uint4* vl4 = (const uint4*)(g_Vlo + toff);
            #pragma unroll
            for (int i = tid; i < 512; i += 128) {
                int row = i >> 3, ch = i & 7;
                uint32_t so = (uint32_t)(row * 128 + ((ch ^ (row & 7)) << 4));
                *(uint4*)(sm + T_KHI + so) = kh4[i];
                *(uint4*)(sm + T_KLO + so) = kl4[i];
                *(uint4*)(sm + T_VHI + so) = vh4[i];
                *(uint4*)(sm + T_VLO + so) = vl4[i];
            }
        }
        __syncthreads();

        // ---- GEMM1: S = Qhi*Khi + Qhi*Klo + Qlo*Khi ----
        float sc[8][4];
        #pragma unroll
        for (int i = 0; i < 8; ++i) { sc[i][0] = sc[i][1] = sc[i][2] = sc[i][3] = 0.f; }

        #pragma unroll
        for (int ks = 0; ks < 4; ++ks) {
            #pragma unroll
            for (int p = 0; p < 4; ++p) {
                uint32_t kb[4], kl2[4];
                ldsm4(kh_base + p * 2048 + swzK[ks], kb);
                mma_bf16(sc[2 * p],     qh[ks], kb[0], kb[1]);
                mma_bf16(sc[2 * p + 1], qh[ks], kb[2], kb[3]);
                mma_bf16(sc[2 * p],     ql[ks], kb[0], kb[1]);
                mma_bf16(sc[2 * p + 1], ql[ks], kb[2], kb[3]);
                ldsm4(kl_base + p * 2048 + swzK[ks], kl2);
                mma_bf16(sc[2 * p],     qh[ks], kl2[0], kl2[1]);
                mma_bf16(sc[2 * p + 1], qh[ks], kl2[2], kl2[3]);
            }
        }

        // ---- diagonal mask (last tile only) ----
        if (kt == qt) {
            #pragma unroll
            for (int nt = 0; nt < 8; ++nt) {
                int j0 = nt * 8 + jb, j1 = j0 + 1;
                if (j0 > row0l)     sc[nt][0] = neg_inf();
                if (j1 > row0l)     sc[nt][1] = neg_inf();
                if (j0 > row0l + 8) sc[nt][2] = neg_inf();
                if (j1 > row0l + 8) sc[nt][3] = neg_inf();
            }
        }

        // ---- online softmax ----
        float mx0 = neg_inf(), mx1 = neg_inf();
        #pragma unroll
        for (int nt = 0; nt < 8; ++nt) {
            mx0 = fmaxf(mx0, fmaxf(sc[nt][0], sc[nt][1]));
            mx1 = fmaxf(mx1, fmaxf(sc[nt][2], sc[nt][3]));
        }
        mx0 = fmaxf(mx0, __shfl_xor_sync(0xffffffffu, mx0, 1));
        mx0 = fmaxf(mx0, __shfl_xor_sync(0xffffffffu, mx0, 2));
        mx1 = fmaxf(mx1, __shfl_xor_sync(0xffffffffu, mx1, 1));
        mx1 = fmaxf(mx1, __shfl_xor_sync(0xffffffffu, mx1, 2));

        float nm0 = fmaxf(m0, mx0), nm1 = fmaxf(m1, mx1);
        float a0 = __expf(m0 - nm0), a1 = __expf(m1 - nm1);
        m0 = nm0; m1 = nm1;

        float la0 = 0.f, la1 = 0.f;
        uint32_t pah[4][4], pal[4][4];
        #pragma unroll
        for (int ks = 0; ks < 4; ++ks) {
            #pragma unroll
            for (int h = 0; h < 2; ++h) {
                int nt = 2 * ks + h;
                float p0 = __expf(sc[nt][0] - nm0);
                float p1 = __expf(sc[nt][1] - nm0);
                float p2 = __expf(sc[nt][2] - nm1);
                float p3 = __expf(sc[nt][3] - nm1);
                la0 += p0 + p1;
                la1 += p2 + p3;
                uint32_t h01 = pack_bf16x2(p0, p1);
                uint32_t h23 = pack_bf16x2(p2, p3);
                pah[ks][2 * h]     = h01;
                pah[ks][2 * h + 1] = h23;
                pal[ks][2 * h]     = pack_bf16x2(p0 - bf_lo(h01), p1 - bf_hi(h01));
                pal[ks][2 * h + 1] = pack_bf16x2(p2 - bf_lo(h23), p3 - bf_hi(h23));
            }
        }
        lp0 = lp0 * a0 + la0;
        lp1 = lp1 * a1 + la1;
        #pragma unroll
        for (int nt = 0; nt < 8; ++nt) {
            oc[nt][0] *= a0; oc[nt][1] *= a0;
            oc[nt][2] *= a1; oc[nt][3] *= a1;
        }

        // ---- GEMM2: O += Phi*Vhi + Phi*Vlo + Plo*Vhi ----
        #pragma unroll
        for (int ks = 0; ks < 4; ++ks) {
            #pragma unroll
            for (int p = 0; p < 4; ++p) {
                uint32_t vb[4], vl2[4];
                ldsm4t(vh_base + ks * 2048 + swzV[p], vb);
                mma_bf16(oc[2 * p],     pah[ks], vb[0], vb[1]);
                mma_bf16(oc[2 * p + 1], pah[ks], vb[2], vb[3]);
                mma_bf16(oc[2 * p],     pal[ks], vb[0], vb[1]);
                mma_bf16(oc[2 * p + 1], pal[ks], vb[2], vb[3]);
                ldsm4t(vl_base + ks * 2048 + swzV[p], vl2);
                mma_bf16(oc[2 * p],     pah[ks], vl2[0], vl2[1]);
                mma_bf16(oc[2 * p + 1], pah[ks], vl2[2], vl2[3]);
            }
        }
    }

    // ---- epilogue ----
    float l0 = lp0, l1 = lp1;
    l0 += __shfl_xor_sync(0xffffffffu, l0, 1);
    l0 += __shfl_xor_sync(0xffffffffu, l0, 2);
    l1 += __shfl_xor_sync(0xffffffffu, l1, 1);
    l1 += __shfl_xor_sync(0xffffffffu, l1, 2);
    float inv0 = 1.0f / l0, inv1 = 1.0f / l1;

    float* Og = Op + qoff;
    const int rA = warp * 16 + (lane >> 2);
    #pragma unroll
    for (int nt = 0; nt < 8; ++nt) {
        int d = nt * 8 + jb;
        *(float2*)(Og + (size_t)rA * DH + d) =
            make_float2(oc[nt][0] * inv0, oc[nt][1] * inv0);
        *(float2*)(Og + (size_t)(rA + 8) * DH + d) =
            make_float2(oc[nt][2] * inv1, oc[nt][3] * inv1);
    }
}

extern "C" void kernel_launch(void* const* d_in, const int* in_sizes, int n_in,
                              void* d_out, int out_size) {
    const float* keys    = (const float*)d_in[0];
    const float* queries = (const float*)d_in[1];
    const float* values  = (const float*)d_in[2];
    float* out = (float*)d_out;

    dim3 pgrid(NELEM / 4 / 256, 3);           // 4096 x 3
    prepass_kernel<<<pgrid, 256>>>(queries, keys, values);

    dim3 grid(QTILES, BH);                    // 32 x 32
    mha_mma_kernel<<<grid, 128>>>(out);
}